// round 11
// baseline (speedup 1.0000x reference)
#include <cuda_runtime.h>
#include <cuda_fp16.h>
#include <cstdint>

#define B_SZ   16384
#define D_SZ   256
#define H_SZ   8192
#define K_TOP  32
#define CAND_K   36     // min acceptable candidate count at threshold
#define CAND_MAX 96     // candidate buffer cap
#define TK_MARGIN 4     // ulp margin below threshold (covers 2*delta fp16+GEMM err)
#define ROWG   4096     // row-group size (acts slab 64MB -> L2 resident)
#define NGRP   (B_SZ / ROWG)

// select staging
#define RS_BATCH 24
#define RS_PITCH 260    // words per staged row (1040B)
#define SEL_SMEM_FLOATS (256 + CAND_MAX + CAND_MAX + RS_BATCH * RS_PITCH)
#define SEL_SMEM_BYTES  (SEL_SMEM_FLOATS * 4)

// ---------------------------------------------------------------------------
// Scratch (__device__ globals)
// ---------------------------------------------------------------------------
__device__ __half g_xh [B_SZ * D_SZ];                 // fp16(x - b_dec)
__device__ __half g_weh[H_SZ * D_SZ];                 // fp16(W_enc)
__device__ __half g_acts[(size_t)B_SZ * H_SZ];        // fp16 relu(pre_acts)
__device__ int   g_counts[H_SZ];
__device__ float g_colsum[64 * D_SZ];
__device__ float g_qpart[64];
__device__ float g_e2part[B_SZ];                      // per-row e^2

// ---------------------------------------------------------------------------
// Helpers
// ---------------------------------------------------------------------------
__device__ __forceinline__ uint32_t smem_u32(const void* p) {
    uint32_t a;
    asm("{ .reg .u64 t; cvta.to.shared.u64 t, %1; cvt.u32.u64 %0, t; }" : "=r"(a) : "l"(p));
    return a;
}
#define CP_ASYNC16(dst, src) \
    asm volatile("cp.async.cg.shared.global [%0], [%1], 16;" :: "r"(dst), "l"(src))
#define CP_COMMIT() asm volatile("cp.async.commit_group;")
#define CP_WAIT(n)  asm volatile("cp.async.wait_group %0;" :: "n"(n))

__device__ __forceinline__ void ldsm_x4(uint32_t& r0, uint32_t& r1, uint32_t& r2, uint32_t& r3,
                                        uint32_t addr) {
    asm volatile("ldmatrix.sync.aligned.m8n8.x4.shared.b16 {%0,%1,%2,%3}, [%4];"
                 : "=r"(r0), "=r"(r1), "=r"(r2), "=r"(r3) : "r"(addr));
}
__device__ __forceinline__ void mma_16816(float* c, uint32_t a0, uint32_t a1, uint32_t a2,
                                          uint32_t a3, uint32_t b0, uint32_t b1) {
    asm volatile(
        "mma.sync.aligned.m16n8k16.row.col.f32.f16.f16.f32 "
        "{%0,%1,%2,%3}, {%4,%5,%6,%7}, {%8,%9}, {%0,%1,%2,%3};"
        : "+f"(c[0]), "+f"(c[1]), "+f"(c[2]), "+f"(c[3])
        : "r"(a0), "r"(a1), "r"(a2), "r"(a3), "r"(b0), "r"(b1));
}

// ---------------------------------------------------------------------------
// Kernel 0: convert x -> fp16(x - b_dec), W_enc -> fp16
// ---------------------------------------------------------------------------
__global__ __launch_bounds__(256) void conv_kernel(
    const float* __restrict__ x, const float* __restrict__ W_enc,
    const float* __restrict__ b_dec)
{
    int b = blockIdx.x, t = threadIdx.x;
    if (b < 2048) {
        size_t e0 = ((size_t)b * 256 + t) * 8;
        int col = (int)(e0 & (D_SZ - 1));
        float4 v0 = *(const float4*)(x + e0);
        float4 v1 = *(const float4*)(x + e0 + 4);
        float4 d0 = *(const float4*)(b_dec + col);
        float4 d1 = *(const float4*)(b_dec + col + 4);
        __half o[8];
        o[0]=__float2half_rn(v0.x-d0.x); o[1]=__float2half_rn(v0.y-d0.y);
        o[2]=__float2half_rn(v0.z-d0.z); o[3]=__float2half_rn(v0.w-d0.w);
        o[4]=__float2half_rn(v1.x-d1.x); o[5]=__float2half_rn(v1.y-d1.y);
        o[6]=__float2half_rn(v1.z-d1.z); o[7]=__float2half_rn(v1.w-d1.w);
        *(uint4*)(g_xh + e0) = *(uint4*)o;
    } else {
        size_t e0 = ((size_t)(b - 2048) * 256 + t) * 8;
        float4 v0 = *(const float4*)(W_enc + e0);
        float4 v1 = *(const float4*)(W_enc + e0 + 4);
        __half o[8];
        o[0]=__float2half_rn(v0.x); o[1]=__float2half_rn(v0.y);
        o[2]=__float2half_rn(v0.z); o[3]=__float2half_rn(v0.w);
        o[4]=__float2half_rn(v1.x); o[5]=__float2half_rn(v1.y);
        o[6]=__float2half_rn(v1.z); o[7]=__float2half_rn(v1.w);
        *(uint4*)(g_weh + e0) = *(uint4*)o;
    }
}

// ---------------------------------------------------------------------------
// Kernel 1: column stats of x + zero counts
// ---------------------------------------------------------------------------
__global__ __launch_bounds__(256) void colstat_kernel(const float* __restrict__ x)
{
    __shared__ float red[256];
    int g = blockIdx.x, t = threadIdx.x;
    int gid = g * 256 + t;
    if (gid < H_SZ) g_counts[gid] = 0;
    const float* xb = x + (size_t)(g * 256) * D_SZ;
    float s = 0.f, q = 0.f;
    #pragma unroll 8
    for (int r = 0; r < 256; r++) {
        float v = xb[r * D_SZ + t];
        s += v; q += v * v;
    }
    g_colsum[g * D_SZ + t] = s;
    red[t] = q; __syncthreads();
    for (int sft = 128; sft > 0; sft >>= 1) { if (t < sft) red[t] += red[t + sft]; __syncthreads(); }
    if (t == 0) g_qpart[g] = red[0];
}

// ---------------------------------------------------------------------------
// Kernel 2: encoder GEMM via mma.sync (fp16 HMMA), 128x128x256 per block.
// K staged in 4 chunks of 64 (2 buffers); smem 74.2KB -> 2 CTAs/SM.
// ---------------------------------------------------------------------------
#define KC2      64
#define PITCH2   72
#define STG2     (128 * PITCH2 * 2)
#define OFF2_A(p) ((p) * STG2)
#define OFF2_B(p) (2 * STG2 + (p) * STG2)
#define OFF2_BES (4 * STG2)
#define ESM2_TOTAL (OFF2_BES + 512)
#define STAGE_PITCH_U32 68

__global__ __launch_bounds__(256, 2) void encode_kernel(const float* __restrict__ b_enc,
                                                        int rgBase)
{
    extern __shared__ char smem[];
    const uint32_t sbase = smem_u32(smem);
    const int t = threadIdx.x;
    const int wid = t >> 5, lane = t & 31;
    const int h0 = blockIdx.x * 128;
    const int r0 = rgBase + blockIdx.y * 128;

    const int wm = wid >> 2, wn = wid & 3;
    const int m0w = wm * 64, n0w = wn * 32;

    const char* gA = (const char*)(g_xh  + (size_t)r0 * D_SZ);
    const char* gB = (const char*)(g_weh + (size_t)h0 * D_SZ);

    auto load_stage = [&](int s, int p) {
        #pragma unroll
        for (int i = 0; i < 4; i++) {
            int idx = t + 256 * i;
            int row = idx >> 3, q = idx & 7;
            uint32_t dOff = (uint32_t)((row * PITCH2 + q * 8) * 2);
            size_t gOff = ((size_t)row * D_SZ + s * KC2 + q * 8) * 2;
            CP_ASYNC16(sbase + OFF2_A(p) + dOff, gA + gOff);
            CP_ASYNC16(sbase + OFF2_B(p) + dOff, gB + gOff);
        }
        CP_COMMIT();
    };

    load_stage(0, 0);
    load_stage(1, 1);
    ((float*)(smem + OFF2_BES))[t & 127] = b_enc[h0 + (t & 127)];

    float acc[16][4];
    #pragma unroll
    for (int f = 0; f < 16; f++)
        #pragma unroll
        for (int e = 0; e < 4; e++) acc[f][e] = 0.f;

    const int aRow = lane & 15;
    const int aCol = (lane >> 4) << 3;
    const int bRow = ((lane >> 4) << 3) + (lane & 7);
    const int bCol = ((lane >> 3) & 1) << 3;

    CP_WAIT(1);
    __syncthreads();

    #pragma unroll
    for (int s = 0; s < 4; s++) {
        const int p = s & 1;
        const uint32_t aBase = sbase + OFF2_A(p) + ((m0w + aRow) * PITCH2 + aCol) * 2;
        const uint32_t bBase = sbase + OFF2_B(p) + ((n0w + bRow) * PITCH2 + bCol) * 2;
        #pragma unroll
        for (int k0 = 0; k0 < KC2; k0 += 16) {
            uint32_t a[4][4], b[2][4];
            #pragma unroll
            for (int i = 0; i < 4; i++)
                ldsm_x4(a[i][0], a[i][1], a[i][2], a[i][3],
                        aBase + (i * 16 * PITCH2 + k0) * 2);
            #pragma unroll
            for (int jp = 0; jp < 2; jp++)
                ldsm_x4(b[jp][0], b[jp][1], b[jp][2], b[jp][3],
                        bBase + (jp * 16 * PITCH2 + k0) * 2);
            #pragma unroll
            for (int i = 0; i < 4; i++)
                #pragma unroll
                for (int j = 0; j < 4; j++)
                    mma_16816(acc[i * 4 + j], a[i][0], a[i][1], a[i][2], a[i][3],
                              b[j >> 1][(j & 1) * 2], b[j >> 1][(j & 1) * 2 + 1]);
        }
        if (s < 2) {
            __syncthreads();
            load_stage(s + 2, p);
            CP_WAIT(1);
            __syncthreads();
        } else if (s == 2) {
            CP_WAIT(0);
            __syncthreads();
        }
    }
    __syncthreads();

    uint32_t* stg = (uint32_t*)smem;
    const float* bes = (const float*)(smem + OFF2_BES);
    const int qr = lane >> 2, qc = lane & 3;
    #pragma unroll
    for (int i = 0; i < 4; i++) {
        #pragma unroll
        for (int j = 0; j < 4; j++) {
            int col = n0w + j * 8 + qc * 2;
            float b0 = bes[col], b1 = bes[col + 1];
            const float* c = acc[i * 4 + j];
            int mA = m0w + i * 16 + qr;
            float v0 = fmaxf(c[0] + b0, 0.f), v1 = fmaxf(c[1] + b1, 0.f);
            float v2 = fmaxf(c[2] + b0, 0.f), v3 = fmaxf(c[3] + b1, 0.f);
            uint32_t p0 = (uint32_t)__half_as_ushort(__float2half_rn(v0))
                        | ((uint32_t)__half_as_ushort(__float2half_rn(v1)) << 16);
            uint32_t p1 = (uint32_t)__half_as_ushort(__float2half_rn(v2))
                        | ((uint32_t)__half_as_ushort(__float2half_rn(v3)) << 16);
            stg[mA * STAGE_PITCH_U32 + (col >> 1)] = p0;
            stg[(mA + 8) * STAGE_PITCH_U32 + (col >> 1)] = p1;
        }
    }
    __syncthreads();
    #pragma unroll
    for (int i = 0; i < 8; i++) {
        int idx = t + 256 * i;
        int row = idx >> 4, q = idx & 15;
        uint4 v = *(const uint4*)((const char*)stg + row * (STAGE_PITCH_U32 * 4) + q * 16);
        *(uint4*)((char*)g_acts + ((size_t)(r0 + row) * H_SZ + h0) * 2 + q * 16) = v;
    }
}

// ---------------------------------------------------------------------------
// Kernel 3: FUSED select+decode. One block per row:
//   8-threshold SIMD probe (1 barrier) -> candidate collect -> staged exact
//   fp32 rescore (verbatim sequential fmaf) -> rank -> decode columns + counts
//   + per-row e^2. Decode arithmetic identical to the old decode kernel.
// ---------------------------------------------------------------------------
__device__ __forceinline__ int cnt_ge2(const uint32_t* w, uint32_t mid,
                                       volatile int* cwb, int wid, int lane)
{
    uint32_t mm = mid | (mid << 16);
    uint32_t c2 = 0;
    #pragma unroll
    for (int i = 0; i < 16; i++)
        c2 = __vadd2(c2, __vcmpgeu2(w[i], mm) & 0x00010001u);
    unsigned local = (c2 & 0xFFFFu) + (c2 >> 16);
    unsigned r = __reduce_add_sync(0xffffffffu, local);
    if (lane == 0) cwb[wid] = (int)r;
    __syncthreads();
    int s = 0;
    #pragma unroll
    for (int i = 0; i < 8; i++) s += cwb[i];
    return s;
}

__global__ __launch_bounds__(256, 6) void select_kernel(
    const float* __restrict__ x, const float* __restrict__ W_enc,
    const float* __restrict__ b_enc, const float* __restrict__ b_dec,
    const float* __restrict__ W_dec, float* __restrict__ out,
    int rgBase)
{
    extern __shared__ float sm[];
    float* xs  = sm;                       // [256]
    float* cv  = sm + 256;                 // [CAND_MAX]
    int*   ci  = (int*)(sm + 256 + CAND_MAX);
    float* stg = sm + 256 + 2 * CAND_MAX;  // [RS_BATCH][RS_PITCH]; reused as red buf
    __shared__ int cw8[8][8];
    __shared__ int tot[8];
    __shared__ int cwf[2][8];
    __shared__ int s_cnt;
    __shared__ float rv[K_TOP];
    __shared__ int   ri[K_TOP];

    const int row = rgBase + blockIdx.x;
    const int t = threadIdx.x, wid = t >> 5, lane = t & 31;

    const uint4* arow = (const uint4*)((const char*)g_acts + (size_t)row * H_SZ * 2);
    uint4 q[4];
    #pragma unroll
    for (int i = 0; i < 4; i++) q[i] = arow[t + 256 * i];
    uint32_t* w = (uint32_t*)q;            // 32 u16 values

    const float xv  = x[(size_t)row * D_SZ + t];
    const float bdv = b_dec[t];
    xs[t] = xv - bdv;
    if (t == 0) s_cnt = 0;

    // ---- 8-threshold probe: fp16 grid 2.1 .. 2.8 (thresholds sit at 2.4+-0.15)
    const uint32_t TG[8] = {0x4033,0x4066,0x4099,0x40CD,0x4100,0x4133,0x4166,0x419A};
    #pragma unroll
    for (int j = 0; j < 8; j++) {
        uint32_t mm = TG[j] | (TG[j] << 16);
        uint32_t c2 = 0;
        #pragma unroll
        for (int i = 0; i < 16; i++)
            c2 = __vadd2(c2, __vcmpgeu2(w[i], mm) & 0x00010001u);
        unsigned local = (c2 & 0xFFFFu) + (c2 >> 16);
        unsigned r = __reduce_add_sync(0xffffffffu, local);
        if (lane == 0) cw8[wid][j] = (int)r;
    }
    __syncthreads();
    if (t < 8) {
        int s = 0;
        #pragma unroll
        for (int i = 0; i < 8; i++) s += cw8[i][t];
        tot[t] = s;
    }
    __syncthreads();

    int T = -1;
    for (int j = 7; j >= 0; j--) {
        int c = tot[j];
        if (c >= CAND_K) { if (c <= 90) T = (int)TG[j]; break; }
    }
    if (T < 0) {     // rare fallback: full-range exact search for count >= CAND_K
        uint32_t lo = 1, hi = 0x7C00;
        int buf = 0;
        while (hi - lo > 1) {
            uint32_t mid = (lo + hi) >> 1;
            int c = cnt_ge2(w, mid, cwf[buf], wid, lane);
            buf ^= 1;
            if (c >= CAND_K) lo = mid; else hi = mid;
        }
        T = (int)lo;
    }
    const uint32_t Tc = (T > TK_MARGIN) ? (uint32_t)(T - TK_MARGIN) : 1u;

    // ---- collect candidate indices into smem
    #pragma unroll
    for (int i = 0; i < 16; i++) {
        int cbase = (t + 256 * (i >> 2)) * 8 + (i & 3) * 2;
        uint32_t u0 = w[i] & 0xFFFFu, u1 = w[i] >> 16;
        if (u0 >= Tc) {
            int p = atomicAdd(&s_cnt, 1);
            if (p < CAND_MAX) ci[p] = cbase;
        }
        if (u1 >= Tc) {
            int p = atomicAdd(&s_cnt, 1);
            if (p < CAND_MAX) ci[p] = cbase + 1;
        }
    }
    __syncthreads();
    const int cnt = (s_cnt < CAND_MAX) ? s_cnt : CAND_MAX;

    // ---- rescore: staged coalesced, verbatim sequential fmaf chain
    for (int b0 = 0; b0 < cnt; b0 += RS_BATCH) {
        int nb = min(RS_BATCH, cnt - b0);
        for (int j = t; j < nb * 64; j += 256) {
            int r = j >> 6, c4 = j & 63;
            int idx = ci[b0 + r];
            float4 v = __ldg((const float4*)(W_enc + (size_t)idx * D_SZ) + c4);
            *(float4*)(stg + r * RS_PITCH + c4 * 4) = v;
        }
        __syncthreads();
        if (t < nb) {
            int idx = ci[b0 + t];
            const float* wrow = stg + t * RS_PITCH;
            float s = 0.f;
            #pragma unroll 8
            for (int k = 0; k < D_SZ; k++) s = fmaf(xs[k], wrow[k], s);
            cv[b0 + t] = fmaxf(s + b_enc[idx], 0.f);
        }
        __syncthreads();
    }

    // ---- rank -> top-32 (total order: value desc, index asc) + counts
    if (t < cnt) {
        float v = cv[t]; int id = ci[t];
        int rank = 0;
        for (int j = 0; j < cnt; j++) {
            float vo = cv[j];
            rank += (vo > v) || (vo == v && ci[j] < id);
        }
        if (rank < K_TOP) {
            rv[rank] = v;
            ri[rank] = id;
            atomicAdd(&g_counts[id], 1);
        }
    }
    __syncthreads();

    // ---- decode column t (identical arithmetic/order to old decode kernel)
    float acc = bdv;
    #pragma unroll
    for (int j = 0; j < K_TOP; j++)
        acc += rv[j] * __ldg(&W_dec[(size_t)ri[j] * D_SZ + t]);
    out[(size_t)row * D_SZ + t] = acc;

    float e = acc - xv;
    stg[t] = e * e;
    __syncthreads();
    for (int s = 128; s > 0; s >>= 1) {
        if (t < s) stg[t] += stg[t + s];
        __syncthreads();
    }
    if (t == 0) g_e2part[row] = stg[0];
}

// ---------------------------------------------------------------------------
// Kernel 4: finalize
// ---------------------------------------------------------------------------
__global__ __launch_bounds__(256) void finalize_kernel(float* __restrict__ out)
{
    __shared__ float red[256];
    __shared__ float sh_var, sh_q, sh_e2;
    int t = threadIdx.x;
    float S = 0.f;
    for (int g = 0; g < 64; g++) S += g_colsum[g * D_SZ + t];
    red[t] = S * S * (1.0f / (float)B_SZ);
    __syncthreads();
    for (int s = 128; s > 0; s >>= 1) { if (t < s) red[t] += red[t + s]; __syncthreads(); }
    if (t == 0) sh_var = red[0];
    __syncthreads();
    red[t] = (t < 64) ? g_qpart[t] : 0.f;
    __syncthreads();
    for (int s = 128; s > 0; s >>= 1) { if (t < s) red[t] += red[t + s]; __syncthreads(); }
    if (t == 0) sh_q = red[0];
    __syncthreads();
    float e2 = 0.f;
    for (int i = t; i < B_SZ; i += 256) e2 += g_e2part[i];
    red[t] = e2; __syncthreads();
    for (int s = 128; s > 0; s >>= 1) { if (t < s) red[t] += red[t + s]; __syncthreads(); }
    if (t == 0) sh_e2 = red[0];
    __syncthreads();
    if (t == 0) {
        float total_var = sh_q - sh_var;
        out[(size_t)B_SZ * D_SZ + H_SZ] = sh_e2 / total_var;
    }
    for (int i = t; i < H_SZ; i += 256)
        out[(size_t)B_SZ * D_SZ + i] = (float)g_counts[i];
}

// ---------------------------------------------------------------------------
// Launch
// ---------------------------------------------------------------------------
extern "C" void kernel_launch(void* const* d_in, const int* in_sizes, int n_in,
                              void* d_out, int out_size)
{
    const float* x     = (const float*)d_in[0];
    const float* W_enc = (const float*)d_in[1];
    const float* b_enc = (const float*)d_in[2];
    const float* W_dec = (const float*)d_in[3];
    const float* b_dec = (const float*)d_in[4];
    float* out = (float*)d_out;

    cudaFuncSetAttribute(encode_kernel,
                         cudaFuncAttributeMaxDynamicSharedMemorySize, ESM2_TOTAL);
    cudaFuncSetAttribute(select_kernel,
                         cudaFuncAttributeMaxDynamicSharedMemorySize, SEL_SMEM_BYTES);

    conv_kernel<<<3072, 256>>>(x, W_enc, b_dec);
    colstat_kernel<<<64, 256>>>(x);
    for (int g = 0; g < NGRP; g++) {
        int rg = g * ROWG;
        encode_kernel<<<dim3(H_SZ / 128, ROWG / 128), 256, ESM2_TOTAL>>>(b_enc, rg);
        select_kernel<<<ROWG, 256, SEL_SMEM_BYTES>>>(x, W_enc, b_enc, b_dec, W_dec, out, rg);
    }
    finalize_kernel<<<1, 256>>>(out);
}

// round 12
// speedup vs baseline: 1.0561x; 1.0561x over previous
#include <cuda_runtime.h>
#include <cuda_fp16.h>
#include <cstdint>

#define B_SZ   16384
#define D_SZ   256
#define H_SZ   8192
#define K_TOP  32
#define CAND_K   36     // min acceptable candidate count at threshold
#define CAND_MAX 96     // candidate buffer cap
#define TK_MARGIN 4     // ulp margin below threshold (covers 2*delta fp16+GEMM err)
#define ROWG   4096     // row-group size (acts slab 64MB -> L2 resident)
#define NGRP   (B_SZ / ROWG)

// select staging — 16-row batches: smem 18.4KB so 8 CTAs/SM fit
#define RS_BATCH 16
#define RS_PITCH 260    // words per staged row (1040B)
#define SEL_SMEM_FLOATS (256 + CAND_MAX + CAND_MAX + RS_BATCH * RS_PITCH)
#define SEL_SMEM_BYTES  (SEL_SMEM_FLOATS * 4)

// ---------------------------------------------------------------------------
// Scratch (__device__ globals)
// ---------------------------------------------------------------------------
__device__ __half g_xh [B_SZ * D_SZ];                 // fp16(x - b_dec)
__device__ __half g_weh[H_SZ * D_SZ];                 // fp16(W_enc)
__device__ __half g_acts[(size_t)B_SZ * H_SZ];        // fp16 relu(pre_acts)
__device__ int   g_counts[H_SZ];
__device__ float g_colsum[64 * D_SZ];
__device__ float g_qpart[64];
__device__ float g_e2part[B_SZ];                      // per-row e^2

// ---------------------------------------------------------------------------
// Helpers
// ---------------------------------------------------------------------------
__device__ __forceinline__ uint32_t smem_u32(const void* p) {
    uint32_t a;
    asm("{ .reg .u64 t; cvta.to.shared.u64 t, %1; cvt.u32.u64 %0, t; }" : "=r"(a) : "l"(p));
    return a;
}
#define CP_ASYNC16(dst, src) \
    asm volatile("cp.async.cg.shared.global [%0], [%1], 16;" :: "r"(dst), "l"(src))
#define CP_COMMIT() asm volatile("cp.async.commit_group;")
#define CP_WAIT(n)  asm volatile("cp.async.wait_group %0;" :: "n"(n))

__device__ __forceinline__ void ldsm_x4(uint32_t& r0, uint32_t& r1, uint32_t& r2, uint32_t& r3,
                                        uint32_t addr) {
    asm volatile("ldmatrix.sync.aligned.m8n8.x4.shared.b16 {%0,%1,%2,%3}, [%4];"
                 : "=r"(r0), "=r"(r1), "=r"(r2), "=r"(r3) : "r"(addr));
}
__device__ __forceinline__ void mma_16816(float* c, uint32_t a0, uint32_t a1, uint32_t a2,
                                          uint32_t a3, uint32_t b0, uint32_t b1) {
    asm volatile(
        "mma.sync.aligned.m16n8k16.row.col.f32.f16.f16.f32 "
        "{%0,%1,%2,%3}, {%4,%5,%6,%7}, {%8,%9}, {%0,%1,%2,%3};"
        : "+f"(c[0]), "+f"(c[1]), "+f"(c[2]), "+f"(c[3])
        : "r"(a0), "r"(a1), "r"(a2), "r"(a3), "r"(b0), "r"(b1));
}

// ---------------------------------------------------------------------------
// Kernel 0: convert x -> fp16(x - b_dec), W_enc -> fp16
// ---------------------------------------------------------------------------
__global__ __launch_bounds__(256) void conv_kernel(
    const float* __restrict__ x, const float* __restrict__ W_enc,
    const float* __restrict__ b_dec)
{
    int b = blockIdx.x, t = threadIdx.x;
    if (b < 2048) {
        size_t e0 = ((size_t)b * 256 + t) * 8;
        int col = (int)(e0 & (D_SZ - 1));
        float4 v0 = *(const float4*)(x + e0);
        float4 v1 = *(const float4*)(x + e0 + 4);
        float4 d0 = *(const float4*)(b_dec + col);
        float4 d1 = *(const float4*)(b_dec + col + 4);
        __half o[8];
        o[0]=__float2half_rn(v0.x-d0.x); o[1]=__float2half_rn(v0.y-d0.y);
        o[2]=__float2half_rn(v0.z-d0.z); o[3]=__float2half_rn(v0.w-d0.w);
        o[4]=__float2half_rn(v1.x-d1.x); o[5]=__float2half_rn(v1.y-d1.y);
        o[6]=__float2half_rn(v1.z-d1.z); o[7]=__float2half_rn(v1.w-d1.w);
        *(uint4*)(g_xh + e0) = *(uint4*)o;
    } else {
        size_t e0 = ((size_t)(b - 2048) * 256 + t) * 8;
        float4 v0 = *(const float4*)(W_enc + e0);
        float4 v1 = *(const float4*)(W_enc + e0 + 4);
        __half o[8];
        o[0]=__float2half_rn(v0.x); o[1]=__float2half_rn(v0.y);
        o[2]=__float2half_rn(v0.z); o[3]=__float2half_rn(v0.w);
        o[4]=__float2half_rn(v1.x); o[5]=__float2half_rn(v1.y);
        o[6]=__float2half_rn(v1.z); o[7]=__float2half_rn(v1.w);
        *(uint4*)(g_weh + e0) = *(uint4*)o;
    }
}

// ---------------------------------------------------------------------------
// Kernel 1: column stats of x + zero counts
// ---------------------------------------------------------------------------
__global__ __launch_bounds__(256) void colstat_kernel(const float* __restrict__ x)
{
    __shared__ float red[256];
    int g = blockIdx.x, t = threadIdx.x;
    int gid = g * 256 + t;
    if (gid < H_SZ) g_counts[gid] = 0;
    const float* xb = x + (size_t)(g * 256) * D_SZ;
    float s = 0.f, q = 0.f;
    #pragma unroll 8
    for (int r = 0; r < 256; r++) {
        float v = xb[r * D_SZ + t];
        s += v; q += v * v;
    }
    g_colsum[g * D_SZ + t] = s;
    red[t] = q; __syncthreads();
    for (int sft = 128; sft > 0; sft >>= 1) { if (t < sft) red[t] += red[t + sft]; __syncthreads(); }
    if (t == 0) g_qpart[g] = red[0];
}

// ---------------------------------------------------------------------------
// Kernel 2: encoder GEMM via mma.sync (fp16 HMMA), 128x128x256 per block.
// K staged in 4 chunks of 64 (2 buffers); smem 74.2KB -> 2 CTAs/SM.
// ---------------------------------------------------------------------------
#define KC2      64
#define PITCH2   72
#define STG2     (128 * PITCH2 * 2)
#define OFF2_A(p) ((p) * STG2)
#define OFF2_B(p) (2 * STG2 + (p) * STG2)
#define OFF2_BES (4 * STG2)
#define ESM2_TOTAL (OFF2_BES + 512)
#define STAGE_PITCH_U32 68

__global__ __launch_bounds__(256, 2) void encode_kernel(const float* __restrict__ b_enc,
                                                        int rgBase)
{
    extern __shared__ char smem[];
    const uint32_t sbase = smem_u32(smem);
    const int t = threadIdx.x;
    const int wid = t >> 5, lane = t & 31;
    const int h0 = blockIdx.x * 128;
    const int r0 = rgBase + blockIdx.y * 128;

    const int wm = wid >> 2, wn = wid & 3;
    const int m0w = wm * 64, n0w = wn * 32;

    const char* gA = (const char*)(g_xh  + (size_t)r0 * D_SZ);
    const char* gB = (const char*)(g_weh + (size_t)h0 * D_SZ);

    auto load_stage = [&](int s, int p) {
        #pragma unroll
        for (int i = 0; i < 4; i++) {
            int idx = t + 256 * i;
            int row = idx >> 3, q = idx & 7;
            uint32_t dOff = (uint32_t)((row * PITCH2 + q * 8) * 2);
            size_t gOff = ((size_t)row * D_SZ + s * KC2 + q * 8) * 2;
            CP_ASYNC16(sbase + OFF2_A(p) + dOff, gA + gOff);
            CP_ASYNC16(sbase + OFF2_B(p) + dOff, gB + gOff);
        }
        CP_COMMIT();
    };

    load_stage(0, 0);
    load_stage(1, 1);
    ((float*)(smem + OFF2_BES))[t & 127] = b_enc[h0 + (t & 127)];

    float acc[16][4];
    #pragma unroll
    for (int f = 0; f < 16; f++)
        #pragma unroll
        for (int e = 0; e < 4; e++) acc[f][e] = 0.f;

    const int aRow = lane & 15;
    const int aCol = (lane >> 4) << 3;
    const int bRow = ((lane >> 4) << 3) + (lane & 7);
    const int bCol = ((lane >> 3) & 1) << 3;

    CP_WAIT(1);
    __syncthreads();

    #pragma unroll
    for (int s = 0; s < 4; s++) {
        const int p = s & 1;
        const uint32_t aBase = sbase + OFF2_A(p) + ((m0w + aRow) * PITCH2 + aCol) * 2;
        const uint32_t bBase = sbase + OFF2_B(p) + ((n0w + bRow) * PITCH2 + bCol) * 2;
        #pragma unroll
        for (int k0 = 0; k0 < KC2; k0 += 16) {
            uint32_t a[4][4], b[2][4];
            #pragma unroll
            for (int i = 0; i < 4; i++)
                ldsm_x4(a[i][0], a[i][1], a[i][2], a[i][3],
                        aBase + (i * 16 * PITCH2 + k0) * 2);
            #pragma unroll
            for (int jp = 0; jp < 2; jp++)
                ldsm_x4(b[jp][0], b[jp][1], b[jp][2], b[jp][3],
                        bBase + (jp * 16 * PITCH2 + k0) * 2);
            #pragma unroll
            for (int i = 0; i < 4; i++)
                #pragma unroll
                for (int j = 0; j < 4; j++)
                    mma_16816(acc[i * 4 + j], a[i][0], a[i][1], a[i][2], a[i][3],
                              b[j >> 1][(j & 1) * 2], b[j >> 1][(j & 1) * 2 + 1]);
        }
        if (s < 2) {
            __syncthreads();
            load_stage(s + 2, p);
            CP_WAIT(1);
            __syncthreads();
        } else if (s == 2) {
            CP_WAIT(0);
            __syncthreads();
        }
    }
    __syncthreads();

    uint32_t* stg = (uint32_t*)smem;
    const float* bes = (const float*)(smem + OFF2_BES);
    const int qr = lane >> 2, qc = lane & 3;
    #pragma unroll
    for (int i = 0; i < 4; i++) {
        #pragma unroll
        for (int j = 0; j < 4; j++) {
            int col = n0w + j * 8 + qc * 2;
            float b0 = bes[col], b1 = bes[col + 1];
            const float* c = acc[i * 4 + j];
            int mA = m0w + i * 16 + qr;
            float v0 = fmaxf(c[0] + b0, 0.f), v1 = fmaxf(c[1] + b1, 0.f);
            float v2 = fmaxf(c[2] + b0, 0.f), v3 = fmaxf(c[3] + b1, 0.f);
            uint32_t p0 = (uint32_t)__half_as_ushort(__float2half_rn(v0))
                        | ((uint32_t)__half_as_ushort(__float2half_rn(v1)) << 16);
            uint32_t p1 = (uint32_t)__half_as_ushort(__float2half_rn(v2))
                        | ((uint32_t)__half_as_ushort(__float2half_rn(v3)) << 16);
            stg[mA * STAGE_PITCH_U32 + (col >> 1)] = p0;
            stg[(mA + 8) * STAGE_PITCH_U32 + (col >> 1)] = p1;
        }
    }
    __syncthreads();
    #pragma unroll
    for (int i = 0; i < 8; i++) {
        int idx = t + 256 * i;
        int row = idx >> 4, q = idx & 15;
        uint4 v = *(const uint4*)((const char*)stg + row * (STAGE_PITCH_U32 * 4) + q * 16);
        *(uint4*)((char*)g_acts + ((size_t)(r0 + row) * H_SZ + h0) * 2 + q * 16) = v;
    }
}

// ---------------------------------------------------------------------------
// Kernel 3: FUSED select+decode (R11 logic, 8 CTAs/SM via launch_bounds(256,8)
// and RS_BATCH=16). All arithmetic identical to R11's passing config.
// ---------------------------------------------------------------------------
__device__ __forceinline__ int cnt_ge2(const uint32_t* w, uint32_t mid,
                                       volatile int* cwb, int wid, int lane)
{
    uint32_t mm = mid | (mid << 16);
    uint32_t c2 = 0;
    #pragma unroll
    for (int i = 0; i < 16; i++)
        c2 = __vadd2(c2, __vcmpgeu2(w[i], mm) & 0x00010001u);
    unsigned local = (c2 & 0xFFFFu) + (c2 >> 16);
    unsigned r = __reduce_add_sync(0xffffffffu, local);
    if (lane == 0) cwb[wid] = (int)r;
    __syncthreads();
    int s = 0;
    #pragma unroll
    for (int i = 0; i < 8; i++) s += cwb[i];
    return s;
}

__global__ __launch_bounds__(256, 8) void select_kernel(
    const float* __restrict__ x, const float* __restrict__ W_enc,
    const float* __restrict__ b_enc, const float* __restrict__ b_dec,
    const float* __restrict__ W_dec, float* __restrict__ out,
    int rgBase)
{
    extern __shared__ float sm[];
    float* xs  = sm;                       // [256]
    float* cv  = sm + 256;                 // [CAND_MAX]
    int*   ci  = (int*)(sm + 256 + CAND_MAX);
    float* stg = sm + 256 + 2 * CAND_MAX;  // [RS_BATCH][RS_PITCH]; reused as red buf
    __shared__ int cw8[8][8];
    __shared__ int tot[8];
    __shared__ int cwf[2][8];
    __shared__ int s_cnt;
    __shared__ float rv[K_TOP];
    __shared__ int   ri[K_TOP];

    const int row = rgBase + blockIdx.x;
    const int t = threadIdx.x, wid = t >> 5, lane = t & 31;

    const uint4* arow = (const uint4*)((const char*)g_acts + (size_t)row * H_SZ * 2);
    uint4 q[4];
    #pragma unroll
    for (int i = 0; i < 4; i++) q[i] = arow[t + 256 * i];
    uint32_t* w = (uint32_t*)q;            // 32 u16 values

    const float xv  = x[(size_t)row * D_SZ + t];
    const float bdv = b_dec[t];
    xs[t] = xv - bdv;
    if (t == 0) s_cnt = 0;

    // ---- 8-threshold probe: fp16 grid 2.1 .. 2.8
    const uint32_t TG[8] = {0x4033,0x4066,0x4099,0x40CD,0x4100,0x4133,0x4166,0x419A};
    #pragma unroll
    for (int j = 0; j < 8; j++) {
        uint32_t mm = TG[j] | (TG[j] << 16);
        uint32_t c2 = 0;
        #pragma unroll
        for (int i = 0; i < 16; i++)
            c2 = __vadd2(c2, __vcmpgeu2(w[i], mm) & 0x00010001u);
        unsigned local = (c2 & 0xFFFFu) + (c2 >> 16);
        unsigned r = __reduce_add_sync(0xffffffffu, local);
        if (lane == 0) cw8[wid][j] = (int)r;
    }
    __syncthreads();
    if (t < 8) {
        int s = 0;
        #pragma unroll
        for (int i = 0; i < 8; i++) s += cw8[i][t];
        tot[t] = s;
    }
    __syncthreads();

    int T = -1;
    for (int j = 7; j >= 0; j--) {
        int c = tot[j];
        if (c >= CAND_K) { if (c <= 90) T = (int)TG[j]; break; }
    }
    if (T < 0) {     // rare fallback: full-range exact search for count >= CAND_K
        uint32_t lo = 1, hi = 0x7C00;
        int buf = 0;
        while (hi - lo > 1) {
            uint32_t mid = (lo + hi) >> 1;
            int c = cnt_ge2(w, mid, cwf[buf], wid, lane);
            buf ^= 1;
            if (c >= CAND_K) lo = mid; else hi = mid;
        }
        T = (int)lo;
    }
    const uint32_t Tc = (T > TK_MARGIN) ? (uint32_t)(T - TK_MARGIN) : 1u;

    // ---- collect candidate indices into smem
    #pragma unroll
    for (int i = 0; i < 16; i++) {
        int cbase = (t + 256 * (i >> 2)) * 8 + (i & 3) * 2;
        uint32_t u0 = w[i] & 0xFFFFu, u1 = w[i] >> 16;
        if (u0 >= Tc) {
            int p = atomicAdd(&s_cnt, 1);
            if (p < CAND_MAX) ci[p] = cbase;
        }
        if (u1 >= Tc) {
            int p = atomicAdd(&s_cnt, 1);
            if (p < CAND_MAX) ci[p] = cbase + 1;
        }
    }
    __syncthreads();
    const int cnt = (s_cnt < CAND_MAX) ? s_cnt : CAND_MAX;

    // ---- rescore: staged coalesced, verbatim sequential fmaf chain
    for (int b0 = 0; b0 < cnt; b0 += RS_BATCH) {
        int nb = min(RS_BATCH, cnt - b0);
        for (int j = t; j < nb * 64; j += 256) {
            int r = j >> 6, c4 = j & 63;
            int idx = ci[b0 + r];
            float4 v = __ldg((const float4*)(W_enc + (size_t)idx * D_SZ) + c4);
            *(float4*)(stg + r * RS_PITCH + c4 * 4) = v;
        }
        __syncthreads();
        if (t < nb) {
            int idx = ci[b0 + t];
            const float* wrow = stg + t * RS_PITCH;
            float s = 0.f;
            #pragma unroll 8
            for (int k = 0; k < D_SZ; k++) s = fmaf(xs[k], wrow[k], s);
            cv[b0 + t] = fmaxf(s + b_enc[idx], 0.f);
        }
        __syncthreads();
    }

    // ---- rank -> top-32 (total order: value desc, index asc) + counts
    if (t < cnt) {
        float v = cv[t]; int id = ci[t];
        int rank = 0;
        for (int j = 0; j < cnt; j++) {
            float vo = cv[j];
            rank += (vo > v) || (vo == v && ci[j] < id);
        }
        if (rank < K_TOP) {
            rv[rank] = v;
            ri[rank] = id;
            atomicAdd(&g_counts[id], 1);
        }
    }
    __syncthreads();

    // ---- decode column t (identical arithmetic/order to the decode kernel)
    float acc = bdv;
    #pragma unroll
    for (int j = 0; j < K_TOP; j++)
        acc += rv[j] * __ldg(&W_dec[(size_t)ri[j] * D_SZ + t]);
    out[(size_t)row * D_SZ + t] = acc;

    float e = acc - xv;
    stg[t] = e * e;
    __syncthreads();
    for (int s = 128; s > 0; s >>= 1) {
        if (t < s) stg[t] += stg[t + s];
        __syncthreads();
    }
    if (t == 0) g_e2part[row] = stg[0];
}

// ---------------------------------------------------------------------------
// Kernel 4: finalize
// ---------------------------------------------------------------------------
__global__ __launch_bounds__(256) void finalize_kernel(float* __restrict__ out)
{
    __shared__ float red[256];
    __shared__ float sh_var, sh_q, sh_e2;
    int t = threadIdx.x;
    float S = 0.f;
    for (int g = 0; g < 64; g++) S += g_colsum[g * D_SZ + t];
    red[t] = S * S * (1.0f / (float)B_SZ);
    __syncthreads();
    for (int s = 128; s > 0; s >>= 1) { if (t < s) red[t] += red[t + s]; __syncthreads(); }
    if (t == 0) sh_var = red[0];
    __syncthreads();
    red[t] = (t < 64) ? g_qpart[t] : 0.f;
    __syncthreads();
    for (int s = 128; s > 0; s >>= 1) { if (t < s) red[t] += red[t + s]; __syncthreads(); }
    if (t == 0) sh_q = red[0];
    __syncthreads();
    float e2 = 0.f;
    for (int i = t; i < B_SZ; i += 256) e2 += g_e2part[i];
    red[t] = e2; __syncthreads();
    for (int s = 128; s > 0; s >>= 1) { if (t < s) red[t] += red[t + s]; __syncthreads(); }
    if (t == 0) sh_e2 = red[0];
    __syncthreads();
    if (t == 0) {
        float total_var = sh_q - sh_var;
        out[(size_t)B_SZ * D_SZ + H_SZ] = sh_e2 / total_var;
    }
    for (int i = t; i < H_SZ; i += 256)
        out[(size_t)B_SZ * D_SZ + i] = (float)g_counts[i];
}

// ---------------------------------------------------------------------------
// Launch: encode runs on a second stream, overlapped with select of the
// previous row-group (fork-join events; graph-capture compatible).
// ---------------------------------------------------------------------------
static cudaStream_t g_s2 = nullptr;
static cudaEvent_t  g_evC = nullptr;
static cudaEvent_t  g_evE[NGRP];

extern "C" void kernel_launch(void* const* d_in, const int* in_sizes, int n_in,
                              void* d_out, int out_size)
{
    const float* x     = (const float*)d_in[0];
    const float* W_enc = (const float*)d_in[1];
    const float* b_enc = (const float*)d_in[2];
    const float* W_dec = (const float*)d_in[3];
    const float* b_dec = (const float*)d_in[4];
    float* out = (float*)d_out;

    if (g_s2 == nullptr) {   // one-time host-side resources (created on the
        cudaStreamCreateWithFlags(&g_s2, cudaStreamNonBlocking);   // uncaptured
        cudaEventCreateWithFlags(&g_evC, cudaEventDisableTiming);  // correctness
        for (int g = 0; g < NGRP; g++)                             // call)
            cudaEventCreateWithFlags(&g_evE[g], cudaEventDisableTiming);
        cudaFuncSetAttribute(encode_kernel,
                             cudaFuncAttributeMaxDynamicSharedMemorySize, ESM2_TOTAL);
        cudaFuncSetAttribute(select_kernel,
                             cudaFuncAttributeMaxDynamicSharedMemorySize, SEL_SMEM_BYTES);
    }

    conv_kernel<<<3072, 256>>>(x, W_enc, b_dec);
    colstat_kernel<<<64, 256>>>(x);
    cudaEventRecord(g_evC, 0);
    cudaStreamWaitEvent(g_s2, g_evC, 0);

    encode_kernel<<<dim3(H_SZ / 128, ROWG / 128), 256, ESM2_TOTAL, g_s2>>>(b_enc, 0);
    cudaEventRecord(g_evE[0], g_s2);

    for (int g = 0; g < NGRP; g++) {
        if (g + 1 < NGRP) {
            encode_kernel<<<dim3(H_SZ / 128, ROWG / 128), 256, ESM2_TOTAL, g_s2>>>(
                b_enc, (g + 1) * ROWG);
            cudaEventRecord(g_evE[g + 1], g_s2);
        }
        cudaStreamWaitEvent(0, g_evE[g], 0);
        select_kernel<<<ROWG, 256, SEL_SMEM_BYTES>>>(
            x, W_enc, b_enc, b_dec, W_dec, out, g * ROWG);
    }
    finalize_kernel<<<1, 256>>>(out);
}